// round 1
// baseline (speedup 1.0000x reference)
#include <cuda_runtime.h>
#include <math.h>

#define BB 128   // batch
#define TT 100   // time
#define PD 4096  // proj dim
#define HG 512   // lstm gate dim
#define HD 128   // lstm hidden
#define GH 261   // gru hidden
#define GG 783   // gru gate dim
#define ZD 64    // latent
#define XD 256   // fcin out

// ---- scratch (no allocs allowed) ----
__device__ float g_proj[BB*TT*PD];     // (b*T+t, 4096)
__device__ float g_xg[TT*BB*HG];       // (t, b, 512)
__device__ float g_WhhT[HD*HG];        // (k, g) 128x512
__device__ float g_gWhhT[GH*GG];       // (k, g) 261x783
__device__ float g_hT[BB*HD];
__device__ float g_gxbase[BB*GG];

__device__ __forceinline__ float sigmoidf_(float x){ return 1.0f/(1.0f+expf(-x)); }
__device__ __forceinline__ float leakyf_(float x, float s){ return x >= 0.0f ? x : s*x; }

// K0: transpose recurrent weights for coalesced per-step loads
__global__ void k_prep(const float* __restrict__ lstm_Whh, const float* __restrict__ gru_Whh)
{
    int i = blockIdx.x*blockDim.x + threadIdx.x;
    int stride = gridDim.x*blockDim.x;
    for (int idx = i; idx < HG*HD; idx += stride) {
        int g = idx / HD, k = idx - g*HD;
        g_WhhT[k*HG + g] = lstm_Whh[idx];
    }
    for (int idx = i; idx < GG*GH; idx += stride) {
        int g = idx / GH, k = idx - g*GH;
        g_gWhhT[k*GG + g] = gru_Whh[idx];
    }
}

// K1: proj = leaky(pose @ proj_W^T + b, 0.1), one block per (b,t) row
__global__ void __launch_bounds__(512) k_proj(const float* __restrict__ pose,
                                              const float* __restrict__ W,
                                              const float* __restrict__ bias)
{
    __shared__ float p[9];
    int row = blockIdx.x;
    int tid = threadIdx.x;
    if (tid < 9) p[tid] = pose[row*9 + tid];
    __syncthreads();
#pragma unroll
    for (int i = 0; i < PD/512; i++) {
        int k = tid + i*512;
        const float* w = W + k*9;
        float acc = bias[k];
#pragma unroll
        for (int j = 0; j < 9; j++) acc += w[j]*p[j];
        g_proj[row*PD + k] = leakyf_(acc, 0.1f);
    }
}

// K2: x_gates = proj @ lstm_Wih^T + bih + bhh ; output layout (t,b,g)
#define GM 128
#define GN 128
#define GK 16
__global__ void __launch_bounds__(256, 2) k_gemm(const float* __restrict__ Wih,
                                                 const float* __restrict__ bih,
                                                 const float* __restrict__ bhh)
{
    __shared__ float As[GK][GM+4];
    __shared__ float Bs[GK][GN+4];
    int tid = threadIdx.x;
    int bm = blockIdx.x;   // 0..99
    int bn = blockIdx.y;   // 0..3
    int tx = tid & 15, ty = tid >> 4;
    float acc[8][8];
#pragma unroll
    for (int i = 0; i < 8; i++)
#pragma unroll
        for (int j = 0; j < 8; j++) acc[i][j] = 0.f;

    int lr = tid >> 2;          // 0..63
    int lk = (tid & 3) * 4;     // 0,4,8,12
    const float* Ag = g_proj + bm*GM*PD;
    const float* Wg = Wih + bn*GN*PD;

    for (int k0 = 0; k0 < PD; k0 += GK) {
#pragma unroll
        for (int r = 0; r < 2; r++) {
            int row = lr + r*64;
            float4 va = *(const float4*)(Ag + row*PD + k0 + lk);
            As[lk+0][row] = va.x; As[lk+1][row] = va.y;
            As[lk+2][row] = va.z; As[lk+3][row] = va.w;
            float4 vb = *(const float4*)(Wg + row*PD + k0 + lk);
            Bs[lk+0][row] = vb.x; Bs[lk+1][row] = vb.y;
            Bs[lk+2][row] = vb.z; Bs[lk+3][row] = vb.w;
        }
        __syncthreads();
#pragma unroll
        for (int k = 0; k < GK; k++) {
            float4 a0 = *(const float4*)&As[k][ty*8];
            float4 a1 = *(const float4*)&As[k][ty*8+4];
            float4 b0 = *(const float4*)&Bs[k][tx*8];
            float4 b1 = *(const float4*)&Bs[k][tx*8+4];
            float a[8] = {a0.x,a0.y,a0.z,a0.w,a1.x,a1.y,a1.z,a1.w};
            float b[8] = {b0.x,b0.y,b0.z,b0.w,b1.x,b1.y,b1.z,b1.w};
#pragma unroll
            for (int i = 0; i < 8; i++)
#pragma unroll
                for (int j = 0; j < 8; j++) acc[i][j] += a[i]*b[j];
        }
        __syncthreads();
    }
    // epilogue: add biases, scatter rows (b*T+t) -> (t,b,g)
    float bsum[8];
#pragma unroll
    for (int j = 0; j < 8; j++) {
        int g = bn*GN + tx*8 + j;
        bsum[j] = bih[g] + bhh[g];
    }
#pragma unroll
    for (int i = 0; i < 8; i++) {
        int row = bm*GM + ty*8 + i;
        int b = row / TT;
        int t = row - b*TT;
        float* o = g_xg + t*(BB*HG) + b*HG + bn*GN + tx*8;
        float4 o0 = make_float4(acc[i][0]+bsum[0], acc[i][1]+bsum[1],
                                acc[i][2]+bsum[2], acc[i][3]+bsum[3]);
        float4 o1 = make_float4(acc[i][4]+bsum[4], acc[i][5]+bsum[5],
                                acc[i][6]+bsum[6], acc[i][7]+bsum[7]);
        *(float4*)o = o0;
        *(float4*)(o+4) = o1;
    }
}

// K3: LSTM scan over T; one block handles 2 batch elements (independent)
__global__ void __launch_bounds__(512) k_lstm()
{
    __shared__ float hs[2][HD];
    __shared__ float gs[2][HG];
    int tid = threadIdx.x;
    int b0 = blockIdx.x*2;
    if (tid < HD) { hs[0][tid] = 0.f; hs[1][tid] = 0.f; }
    float c0 = 0.f, c1 = 0.f;
    __syncthreads();
    for (int t = 0; t < TT; t++) {
        const float* xg = g_xg + t*(BB*HG);
        float a0 = xg[b0*HG + tid];
        float a1 = xg[(b0+1)*HG + tid];
        const float* w = g_WhhT + tid;
#pragma unroll 4
        for (int k = 0; k < HD; k++) {
            float wv = w[k*HG];
            a0 += wv*hs[0][k];
            a1 += wv*hs[1][k];
        }
        gs[0][tid] = a0; gs[1][tid] = a1;
        __syncthreads();
        if (tid < HD) {
            float i0 = sigmoidf_(gs[0][tid]);
            float f0 = sigmoidf_(gs[0][HD+tid]);
            float g0 = tanhf(gs[0][2*HD+tid]);
            float o0 = sigmoidf_(gs[0][3*HD+tid]);
            c0 = f0*c0 + i0*g0;
            hs[0][tid] = o0*tanhf(c0);
            float i1 = sigmoidf_(gs[1][tid]);
            float f1 = sigmoidf_(gs[1][HD+tid]);
            float g1 = tanhf(gs[1][2*HD+tid]);
            float o1 = sigmoidf_(gs[1][3*HD+tid]);
            c1 = f1*c1 + i1*g1;
            hs[1][tid] = o1*tanhf(c1);
        }
        __syncthreads();
    }
    if (tid < HD) {
        g_hT[b0*HD+tid]     = hs[0][tid];
        g_hT[(b0+1)*HD+tid] = hs[1][tid];
    }
}

// K4: VAE head + fc_in + time-invariant part of gru input gates. One block per b.
__global__ void __launch_bounds__(256) k_head(
    const float* __restrict__ eps,
    const float* __restrict__ muW, const float* __restrict__ mub,
    const float* __restrict__ lvW, const float* __restrict__ lvb,
    const float* __restrict__ fcW, const float* __restrict__ fcb,
    const float* __restrict__ gWih, const float* __restrict__ gbih,
    float* __restrict__ out)
{
    __shared__ float h[HD];
    __shared__ float mu_s[ZD], lv_s[ZD], emb[ZD];
    __shared__ float xs[XD];
    int b = blockIdx.x, tid = threadIdx.x;
    if (tid < HD) h[tid] = g_hT[b*HD+tid];
    __syncthreads();
    if (tid < 2*ZD) {
        int o = tid & 63;
        const float* W = (tid < ZD) ? (muW + o*HD) : (lvW + o*HD);
        float acc = (tid < ZD) ? mub[o] : lvb[o];
        for (int k = 0; k < HD; k++) acc += W[k]*h[k];
        acc = leakyf_(acc, 0.1f);
        if (tid < ZD) mu_s[o] = acc;
        else          lv_s[o] = fminf(10.f, fmaxf(-10.f, acc));
    }
    __syncthreads();
    if (tid < ZD) {
        float m = mu_s[tid], lv = lv_s[tid];
        out[BB*TT*9 + b*ZD + tid] = m;                 // mu output
        out[BB*TT*9 + BB*ZD + b*ZD + tid] = lv;        // logvar output
        emb[tid] = m + eps[b*ZD+tid]*expf(0.5f*lv);
    }
    __syncthreads();
    {
        float acc = fcb[tid];
        const float* W = fcW + tid*ZD;
        for (int k = 0; k < ZD; k++) acc += W[k]*emb[k];
        xs[tid] = acc;
    }
    __syncthreads();
    for (int g = tid; g < GG; g += 256) {
        float acc = gbih[g];
        const float* W = gWih + g*261;
        for (int k = 0; k < XD; k++) acc += W[k]*xs[k];
        g_gxbase[b*GG+g] = acc;
    }
}

// K5: GRU scan + joint-frame head; one block handles 2 batch elements
__global__ void __launch_bounds__(800) k_gru(
    const float* __restrict__ noise_eps,
    const float* __restrict__ gWih, const float* __restrict__ gbhh,
    const float* __restrict__ W1, const float* __restrict__ b1,
    const float* __restrict__ W2, const float* __restrict__ b2,
    float* __restrict__ out)
{
    __shared__ float hs[2][GH];
    __shared__ float gxs[2][GG];
    __shared__ float ghs[2][GG];
    __shared__ float f1s[2][ZD];
    __shared__ float ns[8];
    int tid = threadIdx.x;
    int b0 = blockIdx.x*2;

    for (int j = tid; j < 2*GH; j += 800) (&hs[0][0])[j] = 0.f;

    float wn0=0,wn1=0,wn2=0,wn3=0,wt=0,bh=0,gx0b=0,gx1b=0;
    if (tid < GG) {
        const float* W = gWih + tid*261;
        wn0=W[256]; wn1=W[257]; wn2=W[258]; wn3=W[259]; wt=W[260];
        bh = gbhh[tid];
        gx0b = g_gxbase[b0*GG+tid];
        gx1b = g_gxbase[(b0+1)*GG+tid];
    }
    __syncthreads();
    const float inv = 1.0f/(float)(TT-1);
    for (int t = 0; t < TT; t++) {
        if (tid < 8) {
            int bb = tid >> 2, j = tid & 3;
            ns[tid] = noise_eps[t*(BB*4) + (b0+bb)*4 + j] * 0.1f;
        }
        __syncthreads();
        if (tid < GG) {
            float tv = (float)t * inv;
            float gx0 = gx0b + wn0*ns[0]+wn1*ns[1]+wn2*ns[2]+wn3*ns[3] + wt*tv;
            float gx1 = gx1b + wn0*ns[4]+wn1*ns[5]+wn2*ns[6]+wn3*ns[7] + wt*tv;
            float a0 = bh, a1 = bh;
            const float* w = g_gWhhT + tid;
#pragma unroll 3
            for (int k = 0; k < GH; k++) {
                float wv = w[k*GG];
                a0 += wv*hs[0][k];
                a1 += wv*hs[1][k];
            }
            gxs[0][tid]=gx0; gxs[1][tid]=gx1;
            ghs[0][tid]=a0;  ghs[1][tid]=a1;
        }
        __syncthreads();
        if (tid < 2*GH) {
            int bb = (tid < GH) ? 0 : 1;
            int j  = tid - bb*GH;
            float r = sigmoidf_(gxs[bb][j]      + ghs[bb][j]);
            float z = sigmoidf_(gxs[bb][GH+j]   + ghs[bb][GH+j]);
            float n = tanhf(gxs[bb][2*GH+j] + r*ghs[bb][2*GH+j]);
            hs[bb][j] = (1.f - z)*n + z*hs[bb][j];
        }
        __syncthreads();
        if (tid < 2*ZD) {
            int bb = tid >> 6, o = tid & 63;
            float acc = b1[o];
            const float* W = W1 + o*GH;
            for (int k = 0; k < GH; k++) acc += W[k]*hs[bb][k];
            f1s[bb][o] = leakyf_(acc, 0.2f);
        }
        __syncthreads();
        if (tid < 18) {
            int bb = tid / 9, i = tid - bb*9;
            float acc = b2[i];
            const float* W = W2 + i*ZD;
            for (int o = 0; o < ZD; o++) acc += W[o]*f1s[bb][o];
            out[(b0+bb)*(TT*9) + t*9 + i] = sigmoidf_(acc);
        }
        // next-iteration sync at loop top guards f1s/ns reuse
    }
}

extern "C" void kernel_launch(void* const* d_in, const int* in_sizes, int n_in,
                              void* d_out, int out_size)
{
    const float* input_data = (const float*)d_in[0];
    const float* eps        = (const float*)d_in[1];
    const float* noise_eps  = (const float*)d_in[2];
    const float* proj_W     = (const float*)d_in[3];
    const float* proj_b     = (const float*)d_in[4];
    const float* lstm_Wih   = (const float*)d_in[5];
    const float* lstm_Whh   = (const float*)d_in[6];
    const float* lstm_bih   = (const float*)d_in[7];
    const float* lstm_bhh   = (const float*)d_in[8];
    const float* mu_W       = (const float*)d_in[9];
    const float* mu_b       = (const float*)d_in[10];
    const float* lv_W       = (const float*)d_in[11];
    const float* lv_b       = (const float*)d_in[12];
    const float* fcin_W     = (const float*)d_in[13];
    const float* fcin_b     = (const float*)d_in[14];
    const float* gru_Wih    = (const float*)d_in[15];
    const float* gru_Whh    = (const float*)d_in[16];
    const float* gru_bih    = (const float*)d_in[17];
    const float* gru_bhh    = (const float*)d_in[18];
    const float* jf_W1      = (const float*)d_in[19];
    const float* jf_b1      = (const float*)d_in[20];
    const float* jf_W2      = (const float*)d_in[21];
    const float* jf_b2      = (const float*)d_in[22];
    float* out = (float*)d_out;

    k_prep<<<64, 256>>>(lstm_Whh, gru_Whh);
    k_proj<<<BB*TT, 512>>>(input_data, proj_W, proj_b);
    dim3 g2(TT*BB/GM, HG/GN);   // (100, 4)
    k_gemm<<<g2, 256>>>(lstm_Wih, lstm_bih, lstm_bhh);
    k_lstm<<<BB/2, 512>>>();
    k_head<<<BB, 256>>>(eps, mu_W, mu_b, lv_W, lv_b, fcin_W, fcin_b,
                        gru_Wih, gru_bih, out);
    k_gru<<<BB/2, 800>>>(noise_eps, gru_Wih, gru_bhh, jf_W1, jf_b1, jf_W2, jf_b2, out);
}